// round 9
// baseline (speedup 1.0000x reference)
#include <cuda_runtime.h>
#include <cuda_fp16.h>
#include <cstdint>

// ---------------- problem constants ----------------
#define BLn    8192      // B * L
#define LSEQ   4096
#define DIMI   2048
#define DINn   8512      // 2*HID + 2*G*N + H
#define HIDC   4096
#define CONVD  4352      // HID + 2*G*N
#define NHh    64        // heads
#define PD     64        // head dim
#define NS     128       // state dim
#define QC     128       // chunk len
#define NCT    64        // total chunks = B * (L/Q)

// ---------------- scratch (device globals; allocation-free rule) ----------------
__device__ float g_zx[(size_t)BLn * DINn];
__device__ float g_conv[(size_t)BLn * CONVD];
__device__ float g_dt[BLn * NHh];
__device__ float g_cum[BLn * NHh];
__device__ float g_CB[NCT * QC * QC];
__device__ float g_states[(size_t)NCT * NHh * PD * NS];
__device__ float g_y[(size_t)BLn * HIDC];

__device__ __forceinline__ void fma4(float4& a, float s, const float4 v) {
    a.x += s * v.x; a.y += s * v.y; a.z += s * v.z; a.w += s * v.w;
}

// =======================================================================
//  DUAL-PIPE GEMM: C[M,N] = A[M,K] * B[N,K]^T, fp32 in/out.
//  CTA-level role split (no register union):
//    blockIdx.x <  nTT : 256x128 tile, fp16 mma.sync (tensor pipe)
//    blockIdx.x >= nTT : 256x64  tile, packed fp32 fma.rn.f32x2 (FMA pipe)
//  Mixed co-resident CTAs use both pipes of an SM concurrently.
// =======================================================================

__device__ __forceinline__ uint32_t pack_h2(float x, float y) {
    uint32_t r;
    asm("cvt.rn.f16x2.f32 %0, %1, %2;" : "=r"(r) : "f"(y), "f"(x));
    return r;
}
__device__ __forceinline__ void mma_f16(float* d, const uint32_t* a, const uint32_t* b) {
    asm volatile(
        "mma.sync.aligned.m16n8k16.row.col.f32.f16.f16.f32 "
        "{%0,%1,%2,%3}, {%4,%5,%6,%7}, {%8,%9}, {%0,%1,%2,%3};"
        : "+f"(d[0]), "+f"(d[1]), "+f"(d[2]), "+f"(d[3])
        : "r"(a[0]), "r"(a[1]), "r"(a[2]), "r"(a[3]), "r"(b[0]), "r"(b[1]));
}
__device__ __forceinline__ void ffma2(uint64_t& d, uint64_t a, uint64_t b) {
    asm("fma.rn.f32x2 %0, %1, %2, %0;" : "+l"(d) : "l"(a), "l"(b));
}
__device__ __forceinline__ uint64_t dupf(float v) {
    uint64_t r; asm("mov.b64 %0, {%1, %1};" : "=l"(r) : "f"(v)); return r;
}
__device__ __forceinline__ uint64_t packf2(float x, float y) {
    uint64_t r; asm("mov.b64 %0, {%1, %2};" : "=l"(r) : "f"(x), "f"(y)); return r;
}

#define AH 20                      // padded row stride (halves or floats)
#define TSTH ((256 + 128) * AH)    // tensor stage: halves = 7680 (15360 B)
#define FSTF ((256 + 64) * AH)     // ffma stage: floats = 6400 (25600 B)
#define DUAL_SMEM (2 * FSTF * 4)   // 51200 B (>= 2*TSTH*2 = 30720)

__global__ void __launch_bounds__(256, 2) gemm_dual(
    const float* __restrict__ A, const float* __restrict__ B, float* __restrict__ C,
    int Nvalid, int K, int ldC, int nTT)
{
    extern __shared__ char smc[];
    const int tid  = threadIdx.x;
    const int bx   = blockIdx.x;
    const int cRow = blockIdx.y * 256;
    const int KT   = K >> 4;
    const int srow = tid >> 2;
    const int kq4  = (tid & 3) * 4;

    if (bx < nTT) {
        // ---------------- tensor role: 256x128 fp16 mma ----------------
        const int cCol = bx * 128;
        __half* hsm = (__half*)smc;
        const int wid = tid >> 5, lane = tid & 31;
        const int gID = lane >> 2, tig = lane & 3;
        const int wM  = (wid >> 1) * 64;
        const int wN  = (wid & 1) * 64;
        bool bok[2];
        bok[0] = (cCol + srow) < Nvalid;
        bok[1] = (cCol + 64 + srow) < Nvalid;

        float acc[4][8][4];
        #pragma unroll
        for (int mi = 0; mi < 4; mi++)
            #pragma unroll
            for (int ni = 0; ni < 8; ni++)
                #pragma unroll
                for (int u = 0; u < 4; u++) acc[mi][ni][u] = 0.f;

        auto store_stage = [&](int slot, const float4* ra, const float4* rb) {
            __half* As = hsm + slot * TSTH;
            __half* Bs = As + 256 * AH;
            #pragma unroll
            for (int v = 0; v < 4; v++) {
                uint2 pk = make_uint2(pack_h2(ra[v].x, ra[v].y), pack_h2(ra[v].z, ra[v].w));
                *reinterpret_cast<uint2*>(&As[(v * 64 + srow) * AH + kq4]) = pk;
            }
            #pragma unroll
            for (int v = 0; v < 2; v++) {
                uint2 pk = make_uint2(pack_h2(rb[v].x, rb[v].y), pack_h2(rb[v].z, rb[v].w));
                *reinterpret_cast<uint2*>(&Bs[(v * 64 + srow) * AH + kq4]) = pk;
            }
        };

        float4 ra[4], rb[2];
        #pragma unroll
        for (int v = 0; v < 4; v++)
            ra[v] = *reinterpret_cast<const float4*>(A + (size_t)(cRow + v * 64 + srow) * K + kq4);
        #pragma unroll
        for (int v = 0; v < 2; v++)
            rb[v] = bok[v] ? *reinterpret_cast<const float4*>(B + (size_t)(cCol + v * 64 + srow) * K + kq4)
                           : make_float4(0.f, 0.f, 0.f, 0.f);
        store_stage(0, ra, rb);
        __syncthreads();

        for (int kt = 0; kt < KT; kt++) {
            const int b = kt & 1;
            const bool more = (kt + 1 < KT);
            if (more) {
                const int kb = (kt + 1) << 4;
                #pragma unroll
                for (int v = 0; v < 4; v++)
                    ra[v] = *reinterpret_cast<const float4*>(A + (size_t)(cRow + v * 64 + srow) * K + kb + kq4);
                #pragma unroll
                for (int v = 0; v < 2; v++)
                    rb[v] = bok[v] ? *reinterpret_cast<const float4*>(B + (size_t)(cCol + v * 64 + srow) * K + kb + kq4)
                                   : make_float4(0.f, 0.f, 0.f, 0.f);
            }
            const __half* As = hsm + b * TSTH;
            const __half* Bs = As + 256 * AH;
            const int k0 = tig * 2;
            uint32_t af[4][4], bf[8][2];
            #pragma unroll
            for (int mi = 0; mi < 4; mi++) {
                const int r = wM + mi * 16 + gID;
                af[mi][0] = *reinterpret_cast<const uint32_t*>(&As[r * AH + k0]);
                af[mi][1] = *reinterpret_cast<const uint32_t*>(&As[(r + 8) * AH + k0]);
                af[mi][2] = *reinterpret_cast<const uint32_t*>(&As[r * AH + k0 + 8]);
                af[mi][3] = *reinterpret_cast<const uint32_t*>(&As[(r + 8) * AH + k0 + 8]);
            }
            #pragma unroll
            for (int ni = 0; ni < 8; ni++) {
                const int r = wN + ni * 8 + gID;
                bf[ni][0] = *reinterpret_cast<const uint32_t*>(&Bs[r * AH + k0]);
                bf[ni][1] = *reinterpret_cast<const uint32_t*>(&Bs[r * AH + k0 + 8]);
            }
            #pragma unroll
            for (int mi = 0; mi < 4; mi++)
                #pragma unroll
                for (int ni = 0; ni < 8; ni++)
                    mma_f16(acc[mi][ni], af[mi], bf[ni]);
            if (more) store_stage(b ^ 1, ra, rb);
            __syncthreads();
        }

        #pragma unroll
        for (int mi = 0; mi < 4; mi++) {
            const int r0 = cRow + wM + mi * 16 + gID;
            #pragma unroll
            for (int ni = 0; ni < 8; ni++) {
                const int c = cCol + wN + ni * 8 + tig * 2;
                if (c < Nvalid) {
                    *reinterpret_cast<float2*>(C + (size_t)r0 * ldC + c) =
                        make_float2(acc[mi][ni][0], acc[mi][ni][1]);
                    *reinterpret_cast<float2*>(C + (size_t)(r0 + 8) * ldC + c) =
                        make_float2(acc[mi][ni][2], acc[mi][ni][3]);
                }
            }
        }
    } else {
        // ---------------- ffma role: 256x64 packed-fp32 SIMT ----------------
        const int cCol = nTT * 128 + (bx - nTT) * 64;
        float* fs = (float*)smc;
        const int tr = tid >> 3;          // 0..31 (8-row group)
        const int tc = tid & 7;           // 0..7  (8-col group)
        const bool bokf = (cCol + srow) < Nvalid;   // srow in 0..63 for B

        uint64_t accF[8][4];
        #pragma unroll
        for (int i = 0; i < 8; i++)
            #pragma unroll
            for (int jj = 0; jj < 4; jj++) accF[i][jj] = 0ull;

        auto store_f = [&](int slot, const float4* ra, float4 rbv) {
            float* As2 = fs + slot * FSTF;
            float* Bs2 = As2 + 256 * AH;
            #pragma unroll
            for (int v = 0; v < 4; v++)
                *reinterpret_cast<float4*>(&As2[(v * 64 + srow) * AH + kq4]) = ra[v];
            *reinterpret_cast<float4*>(&Bs2[srow * AH + kq4]) = rbv;
        };

        float4 ra[4]; float4 rbv;
        #pragma unroll
        for (int v = 0; v < 4; v++)
            ra[v] = *reinterpret_cast<const float4*>(A + (size_t)(cRow + v * 64 + srow) * K + kq4);
        rbv = bokf ? *reinterpret_cast<const float4*>(B + (size_t)(cCol + srow) * K + kq4)
                   : make_float4(0.f, 0.f, 0.f, 0.f);
        store_f(0, ra, rbv);
        __syncthreads();

        for (int kt = 0; kt < KT; kt++) {
            const int b = kt & 1;
            const bool more = (kt + 1 < KT);
            if (more) {
                const int kb = (kt + 1) << 4;
                #pragma unroll
                for (int v = 0; v < 4; v++)
                    ra[v] = *reinterpret_cast<const float4*>(A + (size_t)(cRow + v * 64 + srow) * K + kb + kq4);
                rbv = bokf ? *reinterpret_cast<const float4*>(B + (size_t)(cCol + srow) * K + kb + kq4)
                           : make_float4(0.f, 0.f, 0.f, 0.f);
            }
            const float* As2 = fs + b * FSTF;
            const float* Bs2 = As2 + 256 * AH;
            #pragma unroll
            for (int k = 0; k < 16; k++) {
                float av[8], bv[8];
                #pragma unroll
                for (int i = 0; i < 8; i++) av[i] = As2[(tr * 8 + i) * AH + k];
                #pragma unroll
                for (int j = 0; j < 8; j++) bv[j] = Bs2[(tc * 8 + j) * AH + k];
                uint64_t bp[4];
                #pragma unroll
                for (int jj = 0; jj < 4; jj++) bp[jj] = packf2(bv[2 * jj], bv[2 * jj + 1]);
                #pragma unroll
                for (int i = 0; i < 8; i++) {
                    const uint64_t ad = dupf(av[i]);
                    ffma2(accF[i][0], ad, bp[0]);
                    ffma2(accF[i][1], ad, bp[1]);
                    ffma2(accF[i][2], ad, bp[2]);
                    ffma2(accF[i][3], ad, bp[3]);
                }
            }
            if (more) store_f(b ^ 1, ra, rbv);
            __syncthreads();
        }

        #pragma unroll
        for (int i = 0; i < 8; i++) {
            const int r = cRow + tr * 8 + i;
            #pragma unroll
            for (int jj = 0; jj < 4; jj++) {
                const int c = cCol + tc * 8 + jj * 2;
                if (c < Nvalid)
                    *reinterpret_cast<uint64_t*>(C + (size_t)r * ldC + c) = accF[i][jj];
            }
        }
    }
}

// ---------------- causal depthwise conv (K=4) + SiLU ----------------
__global__ void __launch_bounds__(256) conv_silu_kernel(const float* __restrict__ w) {
    size_t idx = (size_t)blockIdx.x * 256 + threadIdx.x;
    int c = (int)(idx % CONVD);
    int bl = (int)(idx / CONVD);
    int l = bl & (LSEQ - 1);
    float acc = 0.f;
    #pragma unroll
    for (int k = 0; k < 4; k++) {
        int lo = l - 3 + k;
        if (lo >= 0)
            acc += g_zx[(size_t)(bl - 3 + k) * DINn + HIDC + c] * w[c * 4 + k];
    }
    float s = 1.f / (1.f + expf(-acc));
    g_conv[(size_t)bl * CONVD + c] = acc * s;
}

// ---------------- dt = softplus(dt_raw + bias) ----------------
__global__ void __launch_bounds__(256) dt_kernel(const float* __restrict__ dt_bias) {
    int idx = blockIdx.x * 256 + threadIdx.x;
    int h = idx & 63;
    int bl = idx >> 6;
    float v = g_zx[(size_t)bl * DINn + (HIDC + CONVD) + h] + dt_bias[h];
    float d = (v > 20.f) ? v : log1pf(expf(v));
    g_dt[idx] = d;
}

// ---------------- per-chunk cumsum of dt*A (smem staged) ----------------
__global__ void __launch_bounds__(256) cum_kernel(const float* __restrict__ A_log) {
    __shared__ float s[QC * NHh];
    const int ch = blockIdx.x, tid = threadIdx.x;
    for (int idx = tid; idx < QC * NHh; idx += 256)
        s[idx] = g_dt[ch * QC * NHh + idx];
    __syncthreads();
    if (tid < NHh) {
        const float Ax = -expf(A_log[tid]);
        float run = 0.f;
        #pragma unroll 4
        for (int q = 0; q < QC; q++) {
            run += s[q * NHh + tid] * Ax;
            s[q * NHh + tid] = run;
        }
    }
    __syncthreads();
    for (int idx = tid; idx < QC * NHh; idx += 256)
        g_cum[ch * QC * NHh + idx] = s[idx];
}

// ---------------- per-chunk CB[i][j] = sum_n C[i,n]*B[j,n] ----------------
__global__ void __launch_bounds__(256) cb_kernel() {
    extern __shared__ float sh[];
    float* Bsh = sh;             // 128 x 129
    float* Csh = sh + 16512;     // 128 x 129
    int ch = blockIdx.x;
    int tid = threadIdx.x;
    for (int idx = tid; idx < 16384; idx += 256) {
        int i = idx >> 7, n = idx & 127;
        size_t row = (size_t)(ch * QC + i) * CONVD;
        Bsh[i * 129 + n] = g_conv[row + HIDC + n];
        Csh[i * 129 + n] = g_conv[row + HIDC + NS + n];
    }
    __syncthreads();
    int tx = tid & 15, ty = tid >> 4;
    float acc[8][8];
    #pragma unroll
    for (int i = 0; i < 8; i++)
        #pragma unroll
        for (int j = 0; j < 8; j++) acc[i][j] = 0.f;
    for (int n = 0; n < NS; n++) {
        float a[8], b[8];
        #pragma unroll
        for (int u = 0; u < 8; u++) a[u] = Csh[(ty * 8 + u) * 129 + n];
        #pragma unroll
        for (int u = 0; u < 8; u++) b[u] = Bsh[(tx * 8 + u) * 129 + n];
        #pragma unroll
        for (int i = 0; i < 8; i++)
            #pragma unroll
            for (int j = 0; j < 8; j++) acc[i][j] += a[i] * b[j];
    }
    #pragma unroll
    for (int i = 0; i < 8; i++)
        #pragma unroll
        for (int j0 = 0; j0 < 8; j0 += 4)
            *reinterpret_cast<float4*>(&g_CB[ch * 16384 + (ty * 8 + i) * 128 + tx * 8 + j0]) =
                make_float4(acc[i][j0], acc[i][j0 + 1], acc[i][j0 + 2], acc[i][j0 + 3]);
}

// ---------------- chunk states: states[h,p,n] = sum_q wdec[q]*xs[q,p]*B[q,n] ----------------
__global__ void __launch_bounds__(256) states_kernel() {
    __shared__ float Bs[32 * 128];
    __shared__ float xss[32 * 64];
    __shared__ float wdec[128];
    __shared__ float cl;
    const int h = blockIdx.x, ch = blockIdx.y;
    const int tid = threadIdx.x;
    if (tid == 0) cl = g_cum[(ch * QC + QC - 1) * NHh + h];
    __syncthreads();
    if (tid < 128) {
        int r = (ch * QC + tid) * NHh + h;
        wdec[tid] = __expf(cl - g_cum[r]) * g_dt[r];
    }
    const int p = tid >> 2, ng = tid & 3;
    float4 acc4[8];
    #pragma unroll
    for (int u = 0; u < 8; u++) acc4[u] = make_float4(0.f, 0.f, 0.f, 0.f);

    for (int qt = 0; qt < 4; qt++) {
        __syncthreads();
        for (int idx = tid; idx < 4096; idx += 256) {
            int qq = idx >> 7, n = idx & 127;
            Bs[idx] = g_conv[(size_t)(ch * QC + qt * 32 + qq) * CONVD + HIDC + n];
        }
        for (int idx = tid; idx < 2048; idx += 256) {
            int qq = idx >> 6, pp = idx & 63;
            xss[idx] = g_conv[(size_t)(ch * QC + qt * 32 + qq) * CONVD + h * PD + pp];
        }
        __syncthreads();
        #pragma unroll 4
        for (int qq = 0; qq < 32; qq++) {
            float coef = wdec[qt * 32 + qq] * xss[qq * 64 + p];
            const float4* bp = (const float4*)&Bs[qq * 128 + ng * 32];
            #pragma unroll
            for (int u = 0; u < 8; u++) fma4(acc4[u], coef, bp[u]);
        }
    }
    size_t base = ((size_t)ch * NHh + h) * (PD * NS) + (size_t)p * NS + ng * 32;
    #pragma unroll
    for (int u = 0; u < 8; u++)
        *reinterpret_cast<float4*>(&g_states[base + u * 4]) = acc4[u];
}

// ---------------- sequential inter-chunk scan (in-place: states -> Sprev) ----------------
__global__ void __launch_bounds__(256) scan_kernel() {
    const int h = blockIdx.x, b = blockIdx.y;
    const int t = threadIdx.x;
    float S[32];
    #pragma unroll
    for (int i = 0; i < 32; i++) S[i] = 0.f;
    for (int c = 0; c < 32; c++) {
        int ch = b * 32 + c;
        float dec = __expf(g_cum[(ch * QC + QC - 1) * NHh + h]);
        size_t base = ((size_t)ch * NHh + h) * (PD * NS);
        #pragma unroll
        for (int i = 0; i < 32; i++) {
            size_t id = base + (size_t)i * 256 + t;
            float st = g_states[id];
            g_states[id] = S[i];
            S[i] = S[i] * dec + st;
        }
    }
}

// ---------------- Yd + Yoff + D*xs -> y ----------------
__global__ void __launch_bounds__(256) ydyoff_kernel(const float* __restrict__ Dvec) {
    extern __shared__ float sh[];
    float* CBs   = sh;                 // 128 x 129
    float* Cs    = sh + 16512;         // 128 x 129
    float* SpT   = sh + 33024;         // [n][p] 128 x 64
    float* xss   = sh + 41216;         // [j][p] 128 x 64
    float* cum_s = sh + 49408;         // 128
    float* dt_s  = sh + 49536;         // 128
    const int h = blockIdx.x, ch = blockIdx.y, tid = threadIdx.x;

    for (int idx = tid; idx < 16384; idx += 256) {
        int i = idx >> 7, j = idx & 127;
        CBs[i * 129 + j] = g_CB[ch * 16384 + idx];
        Cs[i * 129 + j]  = g_conv[(size_t)(ch * QC + i) * CONVD + HIDC + NS + j];
    }
    for (int idx = tid; idx < 8192; idx += 256) {
        int p = idx >> 7, n = idx & 127;
        SpT[n * 64 + p] = g_states[((size_t)ch * NHh + h) * (PD * NS) + idx];
        xss[idx] = g_conv[(size_t)(ch * QC + (idx >> 6)) * CONVD + h * PD + (idx & 63)];
    }
    if (tid < 128) {
        int r = (ch * QC + tid) * NHh + h;
        cum_s[tid] = g_cum[r];
        dt_s[tid]  = g_dt[r];
    }
    __syncthreads();

    const int i = tid >> 1, ph = tid & 1;
    float4 aD[8], aO[8];
    #pragma unroll
    for (int u = 0; u < 8; u++) { aD[u] = make_float4(0.f,0.f,0.f,0.f); aO[u] = make_float4(0.f,0.f,0.f,0.f); }
    const float ci = cum_s[i];

    for (int j = 0; j <= i; j++) {
        float m = CBs[i * 129 + j] * __expf(ci - cum_s[j]) * dt_s[j];
        const float4* xr = (const float4*)&xss[j * 64 + ph * 32];
        #pragma unroll
        for (int u = 0; u < 8; u++) fma4(aD[u], m, xr[u]);
    }
    #pragma unroll 4
    for (int n = 0; n < NS; n++) {
        float cv = Cs[i * 129 + n];
        const float4* sr = (const float4*)&SpT[n * 64 + ph * 32];
        #pragma unroll
        for (int u = 0; u < 8; u++) fma4(aO[u], cv, sr[u]);
    }
    const float ei = __expf(ci);
    const float Dh = Dvec[h];
    const float* xi = &xss[i * 64 + ph * 32];
    float* yo = &g_y[(size_t)(ch * QC + i) * HIDC + h * PD + ph * 32];
    #pragma unroll
    for (int u = 0; u < 8; u++) {
        float4 d = aD[u], o = aO[u];
        float4 r;
        r.x = d.x + ei * o.x + Dh * xi[u * 4 + 0];
        r.y = d.y + ei * o.y + Dh * xi[u * 4 + 1];
        r.z = d.z + ei * o.z + Dh * xi[u * 4 + 2];
        r.w = d.w + ei * o.w + Dh * xi[u * 4 + 3];
        *reinterpret_cast<float4*>(&yo[u * 4]) = r;
    }
}

// ---------------- gate with silu(z) + RMSNorm (in-place on g_y) ----------------
__global__ void __launch_bounds__(256) gating_kernel(const float* __restrict__ norm_w) {
    __shared__ float red[256];
    const int bl = blockIdx.x, tid = threadIdx.x;
    float vals[16];
    float ss = 0.f;
    #pragma unroll
    for (int it = 0; it < 16; it++) {
        int idx = it * 256 + tid;
        float yv = g_y[(size_t)bl * HIDC + idx];
        float z  = g_zx[(size_t)bl * DINn + idx];
        float yz = yv * (z / (1.f + expf(-z)));
        vals[it] = yz;
        ss += yz * yz;
    }
    red[tid] = ss;
    __syncthreads();
    for (int s = 128; s > 0; s >>= 1) {
        if (tid < s) red[tid] += red[tid + s];
        __syncthreads();
    }
    float sc = rsqrtf(red[0] / (float)HIDC + 1e-5f);
    #pragma unroll
    for (int it = 0; it < 16; it++) {
        int idx = it * 256 + tid;
        g_y[(size_t)bl * HIDC + idx] = vals[it] * sc * norm_w[idx];
    }
}

// ---------------- launch ----------------
extern "C" void kernel_launch(void* const* d_in, const int* in_sizes, int n_in,
                              void* d_out, int out_size) {
    const float* x       = (const float*)d_in[0];
    const float* W_in    = (const float*)d_in[1];
    const float* conv_w  = (const float*)d_in[2];
    const float* dt_bias = (const float*)d_in[3];
    const float* A_log   = (const float*)d_in[4];
    const float* Dv      = (const float*)d_in[5];
    const float* norm_w  = (const float*)d_in[6];
    const float* W_out   = (const float*)d_in[7];
    float* out = (float*)d_out;

    float *zx_p, *y_p;
    cudaGetSymbolAddress((void**)&zx_p, g_zx);
    cudaGetSymbolAddress((void**)&y_p, g_y);

    static cudaStream_t s2 = nullptr;
    static cudaEvent_t evA = nullptr, evB = nullptr;
    if (s2 == nullptr) {
        cudaStreamCreateWithFlags(&s2, cudaStreamNonBlocking);
        cudaEventCreateWithFlags(&evA, cudaEventDisableTiming);
        cudaEventCreateWithFlags(&evB, cudaEventDisableTiming);
        cudaFuncSetAttribute(gemm_dual, cudaFuncAttributeMaxDynamicSharedMemorySize, DUAL_SMEM);
        cudaFuncSetAttribute(cb_kernel, cudaFuncAttributeMaxDynamicSharedMemorySize, 132096);
        cudaFuncSetAttribute(ydyoff_kernel, cudaFuncAttributeMaxDynamicSharedMemorySize, 198656);
    }

    // 1a) in-proj GEMM, xBC+dt columns [4096, 8512): N=4416 = 23*128 + 23*64
    gemm_dual<<<dim3(46, 32), 256, DUAL_SMEM>>>(
        x, W_in + (size_t)HIDC * DIMI, zx_p + HIDC, DINn - HIDC, DIMI, DINn, 23);
    cudaEventRecord(evA, 0);

    // 1b) in-proj GEMM, z columns [0, 4096): N=4096 = 21*128 + 22*64 — side stream
    cudaStreamWaitEvent(s2, evA, 0);
    gemm_dual<<<dim3(43, 32), 256, DUAL_SMEM, s2>>>(
        x, W_in, zx_p, HIDC, DIMI, DINn, 21);
    cudaEventRecord(evB, s2);

    // mid-chain on default stream (concurrent with 1b)
    conv_silu_kernel<<<(BLn * CONVD) / 256, 256>>>(conv_w);
    dt_kernel<<<(BLn * NHh) / 256, 256>>>(dt_bias);
    cum_kernel<<<NCT, 256>>>(A_log);
    cb_kernel<<<NCT, 256, 132096>>>();
    states_kernel<<<dim3(NHh, NCT), 256>>>();
    scan_kernel<<<dim3(NHh, 2), 256>>>();
    ydyoff_kernel<<<dim3(NHh, NCT), 256, 198656>>>(Dv);

    // join: gating needs z columns from 1b
    cudaStreamWaitEvent(0, evB, 0);
    gating_kernel<<<BLn, 256>>>(norm_w);

    // 2) out-proj GEMM: N=2048 = 11*128 + 10*64
    gemm_dual<<<dim3(21, 32), 256, DUAL_SMEM>>>(y_p, W_out, out, DIMI, HIDC, DIMI, 11);
}

// round 10
// speedup vs baseline: 2.0185x; 2.0185x over previous
#include <cuda_runtime.h>
#include <cuda_fp16.h>
#include <cstdint>

// ---------------- problem constants ----------------
#define BLn    8192      // B * L
#define LSEQ   4096
#define DIMI   2048
#define DINn   8512      // 2*HID + 2*G*N + H
#define HIDC   4096
#define CONVD  4352      // HID + 2*G*N
#define NHh    64        // heads
#define PD     64        // head dim
#define NS     128       // state dim
#define QC     128       // chunk len
#define NCT    64        // total chunks = B * (L/Q)

// ---------------- scratch (device globals; allocation-free rule) ----------------
__device__ float g_zx[(size_t)BLn * DINn];
__device__ float g_conv[(size_t)BLn * CONVD];
__device__ float g_dt[BLn * NHh];
__device__ float g_cum[BLn * NHh];
__device__ float g_CB[NCT * QC * QC];
__device__ float g_states[(size_t)NCT * NHh * PD * NS];
__device__ float g_y[(size_t)BLn * HIDC];

__device__ __forceinline__ void fma4(float4& a, float s, const float4 v) {
    a.x += s * v.x; a.y += s * v.y; a.z += s * v.z; a.w += s * v.w;
}

// =======================================================================
//  MIXED-PIPE GEMM: C[M,N] = A[M,K]*B[N,K]^T, fp32 in/out, N % 64 == 0.
//  All tiles are 256x64 (equal work). CTA role by blockIdx.x:
//    bx <  nTT : fp16 mma.sync m16n8k16   (tensor pipe)
//    bx >= nTT : packed fp32 fma.rn.f32x2 (FMA pipe), conflict-free k-major smem
//  __launch_bounds__(256,2) -> 2 CTAs/SM -> mixed co-residency uses both pipes.
// =======================================================================

__device__ __forceinline__ uint32_t pack_h2(float x, float y) {
    uint32_t r;
    asm("cvt.rn.f16x2.f32 %0, %1, %2;" : "=r"(r) : "f"(y), "f"(x));
    return r;
}
__device__ __forceinline__ void mma_f16(float* d, const uint32_t* a, const uint32_t* b) {
    asm volatile(
        "mma.sync.aligned.m16n8k16.row.col.f32.f16.f16.f32 "
        "{%0,%1,%2,%3}, {%4,%5,%6,%7}, {%8,%9}, {%0,%1,%2,%3};"
        : "+f"(d[0]), "+f"(d[1]), "+f"(d[2]), "+f"(d[3])
        : "r"(a[0]), "r"(a[1]), "r"(a[2]), "r"(a[3]), "r"(b[0]), "r"(b[1]));
}
__device__ __forceinline__ void ffma2(uint64_t& d, uint64_t a, uint64_t b) {
    asm("fma.rn.f32x2 %0, %1, %2, %0;" : "+l"(d) : "l"(a), "l"(b));
}
__device__ __forceinline__ uint64_t dupf(float v) {
    uint64_t r; asm("mov.b64 %0, {%1, %1};" : "=l"(r) : "f"(v)); return r;
}

// tensor-role smem (halves): [A 256 x 20 | B 64 x 20] x 2 stages
#define AH   20
#define TSTH ((256 + 64) * AH)            // 6400 halves / stage (12800 B)
// ffma-role smem (floats, k-major): As[k][256] pad 264, Bs[k][64] pad 72
#define FAS  264
#define FBS  72
#define FSTF (16 * (FAS + FBS))           // 5376 floats / stage (21504 B)
#define MIX_SMEM (2 * FSTF * 4)           // 43008 B  (>= 2*TSTH*2 = 25600)

__global__ void __launch_bounds__(256, 2) gemm_mix(
    const float* __restrict__ A, const float* __restrict__ B, float* __restrict__ C,
    int K, int ldC, int nTT)
{
    extern __shared__ char smc[];
    const int tid  = threadIdx.x;
    const int cRow = blockIdx.y * 256;
    const int cCol = blockIdx.x * 64;     // both roles: 64-wide tiles
    const int KT   = K >> 4;
    const int srow = tid >> 2;            // 0..63
    const int kq4  = (tid & 3) * 4;

    if ((int)blockIdx.x < nTT) {
        // ================= tensor role: 256x64 fp16 mma =================
        __half* hsm = (__half*)smc;
        const int wid = tid >> 5, lane = tid & 31;
        const int gID = lane >> 2, tig = lane & 3;
        const int wM  = (wid >> 1) * 64;
        const int wN  = (wid & 1) * 32;

        float acc[4][4][4];
        #pragma unroll
        for (int mi = 0; mi < 4; mi++)
            #pragma unroll
            for (int ni = 0; ni < 4; ni++)
                #pragma unroll
                for (int u = 0; u < 4; u++) acc[mi][ni][u] = 0.f;

        auto store_t = [&](int slot, const float4* ra, float4 rbv) {
            __half* As = hsm + slot * TSTH;
            __half* Bs = As + 256 * AH;
            #pragma unroll
            for (int v = 0; v < 4; v++) {
                uint2 pk = make_uint2(pack_h2(ra[v].x, ra[v].y), pack_h2(ra[v].z, ra[v].w));
                *reinterpret_cast<uint2*>(&As[(v * 64 + srow) * AH + kq4]) = pk;
            }
            uint2 pk = make_uint2(pack_h2(rbv.x, rbv.y), pack_h2(rbv.z, rbv.w));
            *reinterpret_cast<uint2*>(&Bs[srow * AH + kq4]) = pk;
        };

        float4 ra[4], rbv;
        #pragma unroll
        for (int v = 0; v < 4; v++)
            ra[v] = *reinterpret_cast<const float4*>(A + (size_t)(cRow + v * 64 + srow) * K + kq4);
        rbv = *reinterpret_cast<const float4*>(B + (size_t)(cCol + srow) * K + kq4);
        store_t(0, ra, rbv);
        __syncthreads();

        for (int kt = 0; kt < KT; kt++) {
            const int b = kt & 1;
            const bool more = (kt + 1 < KT);
            if (more) {
                const int kb = (kt + 1) << 4;
                #pragma unroll
                for (int v = 0; v < 4; v++)
                    ra[v] = *reinterpret_cast<const float4*>(A + (size_t)(cRow + v * 64 + srow) * K + kb + kq4);
                rbv = *reinterpret_cast<const float4*>(B + (size_t)(cCol + srow) * K + kb + kq4);
            }
            const __half* As = hsm + b * TSTH;
            const __half* Bs = As + 256 * AH;
            const int k0 = tig * 2;
            uint32_t af[4][4], bf[4][2];
            #pragma unroll
            for (int mi = 0; mi < 4; mi++) {
                const int r = wM + mi * 16 + gID;
                af[mi][0] = *reinterpret_cast<const uint32_t*>(&As[r * AH + k0]);
                af[mi][1] = *reinterpret_cast<const uint32_t*>(&As[(r + 8) * AH + k0]);
                af[mi][2] = *reinterpret_cast<const uint32_t*>(&As[r * AH + k0 + 8]);
                af[mi][3] = *reinterpret_cast<const uint32_t*>(&As[(r + 8) * AH + k0 + 8]);
            }
            #pragma unroll
            for (int ni = 0; ni < 4; ni++) {
                const int r = wN + ni * 8 + gID;
                bf[ni][0] = *reinterpret_cast<const uint32_t*>(&Bs[r * AH + k0]);
                bf[ni][1] = *reinterpret_cast<const uint32_t*>(&Bs[r * AH + k0 + 8]);
            }
            #pragma unroll
            for (int mi = 0; mi < 4; mi++)
                #pragma unroll
                for (int ni = 0; ni < 4; ni++)
                    mma_f16(acc[mi][ni], af[mi], bf[ni]);
            if (more) store_t(b ^ 1, ra, rbv);
            __syncthreads();
        }

        #pragma unroll
        for (int mi = 0; mi < 4; mi++) {
            const int r0 = cRow + wM + mi * 16 + gID;
            #pragma unroll
            for (int ni = 0; ni < 4; ni++) {
                const int c = cCol + wN + ni * 8 + tig * 2;
                *reinterpret_cast<float2*>(C + (size_t)r0 * ldC + c) =
                    make_float2(acc[mi][ni][0], acc[mi][ni][1]);
                *reinterpret_cast<float2*>(C + (size_t)(r0 + 8) * ldC + c) =
                    make_float2(acc[mi][ni][2], acc[mi][ni][3]);
            }
        }
    } else {
        // ================= ffma role: 256x64 packed fp32, k-major smem =================
        float* fs = (float*)smc;
        const int tr = tid >> 3;          // 0..31 : rows tr*8..tr*8+7
        const int tc = tid & 7;           // 0..7  : cols tc*8..tc*8+7

        uint64_t acc[8][4];
        #pragma unroll
        for (int i = 0; i < 8; i++)
            #pragma unroll
            for (int jj = 0; jj < 4; jj++) acc[i][jj] = 0ull;

        auto store_f = [&](int slot, const float4* ra, float4 rbv) {
            float* As = fs + slot * FSTF;          // As[k][row], stride FAS
            float* Bs = As + 16 * FAS;             // Bs[k][col], stride FBS
            #pragma unroll
            for (int v = 0; v < 4; v++) {
                const int row = v * 64 + srow;
                As[(kq4 + 0) * FAS + row] = ra[v].x;
                As[(kq4 + 1) * FAS + row] = ra[v].y;
                As[(kq4 + 2) * FAS + row] = ra[v].z;
                As[(kq4 + 3) * FAS + row] = ra[v].w;
            }
            Bs[(kq4 + 0) * FBS + srow] = rbv.x;
            Bs[(kq4 + 1) * FBS + srow] = rbv.y;
            Bs[(kq4 + 2) * FBS + srow] = rbv.z;
            Bs[(kq4 + 3) * FBS + srow] = rbv.w;
        };

        float4 ra[4], rbv;
        #pragma unroll
        for (int v = 0; v < 4; v++)
            ra[v] = *reinterpret_cast<const float4*>(A + (size_t)(cRow + v * 64 + srow) * K + kq4);
        rbv = *reinterpret_cast<const float4*>(B + (size_t)(cCol + srow) * K + kq4);
        store_f(0, ra, rbv);
        __syncthreads();

        for (int kt = 0; kt < KT; kt++) {
            const int b = kt & 1;
            const bool more = (kt + 1 < KT);
            if (more) {
                const int kb = (kt + 1) << 4;
                #pragma unroll
                for (int v = 0; v < 4; v++)
                    ra[v] = *reinterpret_cast<const float4*>(A + (size_t)(cRow + v * 64 + srow) * K + kb + kq4);
                rbv = *reinterpret_cast<const float4*>(B + (size_t)(cCol + srow) * K + kb + kq4);
            }
            const float* As = fs + b * FSTF;
            const float* Bs = As + 16 * FAS;
            #pragma unroll
            for (int kk = 0; kk < 16; kk++) {
                const float* Ak = As + kk * FAS + tr * 8;
                const float* Bk = Bs + kk * FBS + tc * 8;
                float4 a0 = *reinterpret_cast<const float4*>(Ak);
                float4 a1 = *reinterpret_cast<const float4*>(Ak + 4);
                uint64_t bp0 = *reinterpret_cast<const uint64_t*>(Bk);
                uint64_t bp1 = *reinterpret_cast<const uint64_t*>(Bk + 2);
                uint64_t bp2 = *reinterpret_cast<const uint64_t*>(Bk + 4);
                uint64_t bp3 = *reinterpret_cast<const uint64_t*>(Bk + 6);
                float av[8] = { a0.x, a0.y, a0.z, a0.w, a1.x, a1.y, a1.z, a1.w };
                #pragma unroll
                for (int i = 0; i < 8; i++) {
                    const uint64_t ad = dupf(av[i]);
                    ffma2(acc[i][0], ad, bp0);
                    ffma2(acc[i][1], ad, bp1);
                    ffma2(acc[i][2], ad, bp2);
                    ffma2(acc[i][3], ad, bp3);
                }
            }
            if (more) store_f(b ^ 1, ra, rbv);
            __syncthreads();
        }

        #pragma unroll
        for (int i = 0; i < 8; i++) {
            const int r = cRow + tr * 8 + i;
            float* Cp = C + (size_t)r * ldC + cCol + tc * 8;
            *reinterpret_cast<uint64_t*>(Cp + 0) = acc[i][0];
            *reinterpret_cast<uint64_t*>(Cp + 2) = acc[i][1];
            *reinterpret_cast<uint64_t*>(Cp + 4) = acc[i][2];
            *reinterpret_cast<uint64_t*>(Cp + 6) = acc[i][3];
        }
    }
}

// ---------------- causal depthwise conv (K=4) + SiLU ----------------
__global__ void __launch_bounds__(256) conv_silu_kernel(const float* __restrict__ w) {
    size_t idx = (size_t)blockIdx.x * 256 + threadIdx.x;
    int c = (int)(idx % CONVD);
    int bl = (int)(idx / CONVD);
    int l = bl & (LSEQ - 1);
    float acc = 0.f;
    #pragma unroll
    for (int k = 0; k < 4; k++) {
        int lo = l - 3 + k;
        if (lo >= 0)
            acc += g_zx[(size_t)(bl - 3 + k) * DINn + HIDC + c] * w[c * 4 + k];
    }
    float s = 1.f / (1.f + expf(-acc));
    g_conv[(size_t)bl * CONVD + c] = acc * s;
}

// ---------------- dt = softplus(dt_raw + bias) ----------------
__global__ void __launch_bounds__(256) dt_kernel(const float* __restrict__ dt_bias) {
    int idx = blockIdx.x * 256 + threadIdx.x;
    int h = idx & 63;
    int bl = idx >> 6;
    float v = g_zx[(size_t)bl * DINn + (HIDC + CONVD) + h] + dt_bias[h];
    float d = (v > 20.f) ? v : log1pf(expf(v));
    g_dt[idx] = d;
}

// ---------------- per-chunk cumsum of dt*A (smem staged) ----------------
__global__ void __launch_bounds__(256) cum_kernel(const float* __restrict__ A_log) {
    __shared__ float s[QC * NHh];
    const int ch = blockIdx.x, tid = threadIdx.x;
    for (int idx = tid; idx < QC * NHh; idx += 256)
        s[idx] = g_dt[ch * QC * NHh + idx];
    __syncthreads();
    if (tid < NHh) {
        const float Ax = -expf(A_log[tid]);
        float run = 0.f;
        #pragma unroll 4
        for (int q = 0; q < QC; q++) {
            run += s[q * NHh + tid] * Ax;
            s[q * NHh + tid] = run;
        }
    }
    __syncthreads();
    for (int idx = tid; idx < QC * NHh; idx += 256)
        g_cum[ch * QC * NHh + idx] = s[idx];
}

// ---------------- per-chunk CB[i][j] = sum_n C[i,n]*B[j,n] ----------------
__global__ void __launch_bounds__(256) cb_kernel() {
    extern __shared__ float sh[];
    float* Bsh = sh;             // 128 x 129
    float* Csh = sh + 16512;     // 128 x 129
    int ch = blockIdx.x;
    int tid = threadIdx.x;
    for (int idx = tid; idx < 16384; idx += 256) {
        int i = idx >> 7, n = idx & 127;
        size_t row = (size_t)(ch * QC + i) * CONVD;
        Bsh[i * 129 + n] = g_conv[row + HIDC + n];
        Csh[i * 129 + n] = g_conv[row + HIDC + NS + n];
    }
    __syncthreads();
    int tx = tid & 15, ty = tid >> 4;
    float acc[8][8];
    #pragma unroll
    for (int i = 0; i < 8; i++)
        #pragma unroll
        for (int j = 0; j < 8; j++) acc[i][j] = 0.f;
    for (int n = 0; n < NS; n++) {
        float a[8], b[8];
        #pragma unroll
        for (int u = 0; u < 8; u++) a[u] = Csh[(ty * 8 + u) * 129 + n];
        #pragma unroll
        for (int u = 0; u < 8; u++) b[u] = Bsh[(tx * 8 + u) * 129 + n];
        #pragma unroll
        for (int i = 0; i < 8; i++)
            #pragma unroll
            for (int j = 0; j < 8; j++) acc[i][j] += a[i] * b[j];
    }
    #pragma unroll
    for (int i = 0; i < 8; i++)
        #pragma unroll
        for (int j0 = 0; j0 < 8; j0 += 4)
            *reinterpret_cast<float4*>(&g_CB[ch * 16384 + (ty * 8 + i) * 128 + tx * 8 + j0]) =
                make_float4(acc[i][j0], acc[i][j0 + 1], acc[i][j0 + 2], acc[i][j0 + 3]);
}

// ---------------- chunk states: states[h,p,n] = sum_q wdec[q]*xs[q,p]*B[q,n] ----------------
__global__ void __launch_bounds__(256) states_kernel() {
    __shared__ float Bs[32 * 128];
    __shared__ float xss[32 * 64];
    __shared__ float wdec[128];
    __shared__ float cl;
    const int h = blockIdx.x, ch = blockIdx.y;
    const int tid = threadIdx.x;
    if (tid == 0) cl = g_cum[(ch * QC + QC - 1) * NHh + h];
    __syncthreads();
    if (tid < 128) {
        int r = (ch * QC + tid) * NHh + h;
        wdec[tid] = __expf(cl - g_cum[r]) * g_dt[r];
    }
    const int p = tid >> 2, ng = tid & 3;
    float4 acc4[8];
    #pragma unroll
    for (int u = 0; u < 8; u++) acc4[u] = make_float4(0.f, 0.f, 0.f, 0.f);

    for (int qt = 0; qt < 4; qt++) {
        __syncthreads();
        for (int idx = tid; idx < 4096; idx += 256) {
            int qq = idx >> 7, n = idx & 127;
            Bs[idx] = g_conv[(size_t)(ch * QC + qt * 32 + qq) * CONVD + HIDC + n];
        }
        for (int idx = tid; idx < 2048; idx += 256) {
            int qq = idx >> 6, pp = idx & 63;
            xss[idx] = g_conv[(size_t)(ch * QC + qt * 32 + qq) * CONVD + h * PD + pp];
        }
        __syncthreads();
        #pragma unroll 4
        for (int qq = 0; qq < 32; qq++) {
            float coef = wdec[qt * 32 + qq] * xss[qq * 64 + p];
            const float4* bp = (const float4*)&Bs[qq * 128 + ng * 32];
            #pragma unroll
            for (int u = 0; u < 8; u++) fma4(acc4[u], coef, bp[u]);
        }
    }
    size_t base = ((size_t)ch * NHh + h) * (PD * NS) + (size_t)p * NS + ng * 32;
    #pragma unroll
    for (int u = 0; u < 8; u++)
        *reinterpret_cast<float4*>(&g_states[base + u * 4]) = acc4[u];
}

// ---------------- sequential inter-chunk scan (in-place: states -> Sprev) ----------------
__global__ void __launch_bounds__(256) scan_kernel() {
    const int h = blockIdx.x, b = blockIdx.y;
    const int t = threadIdx.x;
    float S[32];
    #pragma unroll
    for (int i = 0; i < 32; i++) S[i] = 0.f;
    for (int c = 0; c < 32; c++) {
        int ch = b * 32 + c;
        float dec = __expf(g_cum[(ch * QC + QC - 1) * NHh + h]);
        size_t base = ((size_t)ch * NHh + h) * (PD * NS);
        #pragma unroll
        for (int i = 0; i < 32; i++) {
            size_t id = base + (size_t)i * 256 + t;
            float st = g_states[id];
            g_states[id] = S[i];
            S[i] = S[i] * dec + st;
        }
    }
}

// ---------------- Yd + Yoff + D*xs -> y ----------------
__global__ void __launch_bounds__(256) ydyoff_kernel(const float* __restrict__ Dvec) {
    extern __shared__ float sh[];
    float* CBs   = sh;                 // 128 x 129
    float* Cs    = sh + 16512;         // 128 x 129
    float* SpT   = sh + 33024;         // [n][p] 128 x 64
    float* xss   = sh + 41216;         // [j][p] 128 x 64
    float* cum_s = sh + 49408;         // 128
    float* dt_s  = sh + 49536;         // 128
    const int h = blockIdx.x, ch = blockIdx.y, tid = threadIdx.x;

    for (int idx = tid; idx < 16384; idx += 256) {
        int i = idx >> 7, j = idx & 127;
        CBs[i * 129 + j] = g_CB[ch * 16384 + idx];
        Cs[i * 129 + j]  = g_conv[(size_t)(ch * QC + i) * CONVD + HIDC + NS + j];
    }
    for (int idx = tid; idx < 8192; idx += 256) {
        int p = idx >> 7, n = idx & 127;
        SpT[n * 64 + p] = g_states[((size_t)ch * NHh + h) * (PD * NS) + idx];
        xss[idx] = g_conv[(size_t)(ch * QC + (idx >> 6)) * CONVD + h * PD + (idx & 63)];
    }
    if (tid < 128) {
        int r = (ch * QC + tid) * NHh + h;
        cum_s[tid] = g_cum[r];
        dt_s[tid]  = g_dt[r];
    }
    __syncthreads();

    const int i = tid >> 1, ph = tid & 1;
    float4 aD[8], aO[8];
    #pragma unroll
    for (int u = 0; u < 8; u++) { aD[u] = make_float4(0.f,0.f,0.f,0.f); aO[u] = make_float4(0.f,0.f,0.f,0.f); }
    const float ci = cum_s[i];

    for (int j = 0; j <= i; j++) {
        float m = CBs[i * 129 + j] * __expf(ci - cum_s[j]) * dt_s[j];
        const float4* xr = (const float4*)&xss[j * 64 + ph * 32];
        #pragma unroll
        for (int u = 0; u < 8; u++) fma4(aD[u], m, xr[u]);
    }
    #pragma unroll 4
    for (int n = 0; n < NS; n++) {
        float cv = Cs[i * 129 + n];
        const float4* sr = (const float4*)&SpT[n * 64 + ph * 32];
        #pragma unroll
        for (int u = 0; u < 8; u++) fma4(aO[u], cv, sr[u]);
    }
    const float ei = __expf(ci);
    const float Dh = Dvec[h];
    const float* xi = &xss[i * 64 + ph * 32];
    float* yo = &g_y[(size_t)(ch * QC + i) * HIDC + h * PD + ph * 32];
    #pragma unroll
    for (int u = 0; u < 8; u++) {
        float4 d = aD[u], o = aO[u];
        float4 r;
        r.x = d.x + ei * o.x + Dh * xi[u * 4 + 0];
        r.y = d.y + ei * o.y + Dh * xi[u * 4 + 1];
        r.z = d.z + ei * o.z + Dh * xi[u * 4 + 2];
        r.w = d.w + ei * o.w + Dh * xi[u * 4 + 3];
        *reinterpret_cast<float4*>(&yo[u * 4]) = r;
    }
}

// ---------------- gate with silu(z) + RMSNorm (in-place on g_y) ----------------
__global__ void __launch_bounds__(256) gating_kernel(const float* __restrict__ norm_w) {
    __shared__ float red[256];
    const int bl = blockIdx.x, tid = threadIdx.x;
    float vals[16];
    float ss = 0.f;
    #pragma unroll
    for (int it = 0; it < 16; it++) {
        int idx = it * 256 + tid;
        float yv = g_y[(size_t)bl * HIDC + idx];
        float z  = g_zx[(size_t)bl * DINn + idx];
        float yz = yv * (z / (1.f + expf(-z)));
        vals[it] = yz;
        ss += yz * yz;
    }
    red[tid] = ss;
    __syncthreads();
    for (int s = 128; s > 0; s >>= 1) {
        if (tid < s) red[tid] += red[tid + s];
        __syncthreads();
    }
    float sc = rsqrtf(red[0] / (float)HIDC + 1e-5f);
    #pragma unroll
    for (int it = 0; it < 16; it++) {
        int idx = it * 256 + tid;
        g_y[(size_t)bl * HIDC + idx] = vals[it] * sc * norm_w[idx];
    }
}

// ---------------- launch ----------------
extern "C" void kernel_launch(void* const* d_in, const int* in_sizes, int n_in,
                              void* d_out, int out_size) {
    const float* x       = (const float*)d_in[0];
    const float* W_in    = (const float*)d_in[1];
    const float* conv_w  = (const float*)d_in[2];
    const float* dt_bias = (const float*)d_in[3];
    const float* A_log   = (const float*)d_in[4];
    const float* Dv      = (const float*)d_in[5];
    const float* norm_w  = (const float*)d_in[6];
    const float* W_out   = (const float*)d_in[7];
    float* out = (float*)d_out;

    float *zx_p, *y_p;
    cudaGetSymbolAddress((void**)&zx_p, g_zx);
    cudaGetSymbolAddress((void**)&y_p, g_y);

    static cudaStream_t s2 = nullptr;
    static cudaEvent_t evA = nullptr, evB = nullptr;
    if (s2 == nullptr) {
        cudaStreamCreateWithFlags(&s2, cudaStreamNonBlocking);
        cudaEventCreateWithFlags(&evA, cudaEventDisableTiming);
        cudaEventCreateWithFlags(&evB, cudaEventDisableTiming);
        cudaFuncSetAttribute(gemm_mix, cudaFuncAttributeMaxDynamicSharedMemorySize, MIX_SMEM);
        cudaFuncSetAttribute(cb_kernel, cudaFuncAttributeMaxDynamicSharedMemorySize, 132096);
        cudaFuncSetAttribute(ydyoff_kernel, cudaFuncAttributeMaxDynamicSharedMemorySize, 198656);
    }

    // 1a) in-proj GEMM, xBC+dt columns [4096, 8512): 69 tiles = 46 T + 23 F
    gemm_mix<<<dim3(69, 32), 256, MIX_SMEM>>>(
        x, W_in + (size_t)HIDC * DIMI, zx_p + HIDC, DIMI, DINn, 46);
    cudaEventRecord(evA, 0);

    // 1b) in-proj GEMM, z columns [0, 4096): 64 tiles = 43 T + 21 F — side stream
    cudaStreamWaitEvent(s2, evA, 0);
    gemm_mix<<<dim3(64, 32), 256, MIX_SMEM, s2>>>(
        x, W_in, zx_p, DIMI, DINn, 43);
    cudaEventRecord(evB, s2);

    // mid-chain on default stream (concurrent with 1b)
    conv_silu_kernel<<<(BLn * CONVD) / 256, 256>>>(conv_w);
    dt_kernel<<<(BLn * NHh) / 256, 256>>>(dt_bias);
    cum_kernel<<<NCT, 256>>>(A_log);
    cb_kernel<<<NCT, 256, 132096>>>();
    states_kernel<<<dim3(NHh, NCT), 256>>>();
    scan_kernel<<<dim3(NHh, 2), 256>>>();
    ydyoff_kernel<<<dim3(NHh, NCT), 256, 198656>>>(Dv);

    // join: gating needs z columns from 1b
    cudaStreamWaitEvent(0, evB, 0);
    gating_kernel<<<BLn, 256>>>(norm_w);

    // 2) out-proj GEMM: 32 tiles = 21 T + 11 F
    gemm_mix<<<dim3(32, 32), 256, MIX_SMEM>>>(y_p, W_out, out, HIDC, DIMI, 21);
}

// round 11
// speedup vs baseline: 2.8922x; 1.4329x over previous
#include <cuda_runtime.h>
#include <cuda_fp16.h>
#include <cstdint>

// ---------------- problem constants ----------------
#define BLn    8192      // B * L
#define LSEQ   4096
#define DIMI   2048
#define DINn   8512      // 2*HID + 2*G*N + H
#define HIDC   4096
#define CONVD  4352      // HID + 2*G*N
#define NHh    64        // heads
#define PD     64        // head dim
#define NS     128       // state dim
#define QC     128       // chunk len
#define NCT    64        // total chunks = B * (L/Q)

// ---------------- scratch (device globals; allocation-free rule) ----------------
__device__ float g_zx[(size_t)BLn * DINn];
__device__ float g_conv[(size_t)BLn * CONVD];
__device__ float g_dt[BLn * NHh];
__device__ float g_cum[BLn * NHh];
__device__ float g_CB[NCT * QC * QC];
__device__ float g_states[(size_t)NCT * NHh * PD * NS];
__device__ float g_y[(size_t)BLn * HIDC];

// packed fp32 helpers (bit-identical to two scalar FMAs, half the issue slots)
__device__ __forceinline__ void ffma2(uint64_t& d, uint64_t a, uint64_t b) {
    asm("fma.rn.f32x2 %0, %1, %2, %0;" : "+l"(d) : "l"(a), "l"(b));
}
__device__ __forceinline__ uint64_t dupf(float v) {
    uint64_t r; asm("mov.b64 %0, {%1, %1};" : "=l"(r) : "f"(v)); return r;
}
// acc (float4 as 2x u64) += s * v
__device__ __forceinline__ void fma4p(uint64_t* a2, uint64_t sd, const float4* v) {
    const uint64_t* v2 = reinterpret_cast<const uint64_t*>(v);
    ffma2(a2[0], sd, v2[0]);
    ffma2(a2[1], sd, v2[1]);
}

// =======================================================================
//  fp16 mma.sync m16n8k16 GEMM:  C[M=8192 slice, Nvalid] = A * B^T
//  fp32 in/out, fp16 operands, fp32 accum. CTA tile 256xNT, 8 warps (4x2).
//  (round-7 proven configuration, unchanged)
// =======================================================================

__device__ __forceinline__ uint32_t pack_h2(float x, float y) {
    uint32_t r;
    asm("cvt.rn.f16x2.f32 %0, %1, %2;" : "=r"(r) : "f"(y), "f"(x));
    return r;
}

__device__ __forceinline__ void mma_f16(float* d, const uint32_t* a, const uint32_t* b) {
    asm volatile(
        "mma.sync.aligned.m16n8k16.row.col.f32.f16.f16.f32 "
        "{%0,%1,%2,%3}, {%4,%5,%6,%7}, {%8,%9}, {%0,%1,%2,%3};"
        : "+f"(d[0]), "+f"(d[1]), "+f"(d[2]), "+f"(d[3])
        : "r"(a[0]), "r"(a[1]), "r"(a[2]), "r"(a[3]), "r"(b[0]), "r"(b[1]));
}

#define AH 20                                 // half stride per smem row (16 + pad 4)

template<int NT>
__global__ void __launch_bounds__(256) gemm_tc(
    const float* __restrict__ A, const float* __restrict__ B, float* __restrict__ C,
    int Nvalid, int K, int ldC)
{
    constexpr int NFRAG = NT / 16;            // n8-frags per warp
    constexpr int NB    = NT / 64;            // B staging v-iters
    constexpr int SSTH  = (256 + NT) * AH;    // halves per stage
    extern __shared__ __half hsm[];
    const int tid  = threadIdx.x;
    const int wid  = tid >> 5, lane = tid & 31;
    const int gID  = lane >> 2, tig = lane & 3;
    const int wM   = (wid >> 1) * 64;
    const int wN   = (wid & 1) * (NT / 2);
    const int cRow = blockIdx.y * 256;
    const int cCol = blockIdx.x * NT;
    const int KT   = K >> 4;

    const int srow = tid >> 2;
    const int sc4  = (tid & 3) * 4;
    bool bok[NB];
    #pragma unroll
    for (int v = 0; v < NB; v++) bok[v] = (cCol + v * 64 + srow) < Nvalid;

    float acc[4][NFRAG][4];
    #pragma unroll
    for (int mi = 0; mi < 4; mi++)
        #pragma unroll
        for (int ni = 0; ni < NFRAG; ni++)
            #pragma unroll
            for (int u = 0; u < 4; u++) acc[mi][ni][u] = 0.f;

    auto store_stage = [&](int slot, const float4* ra, const float4* rb) {
        __half* As = hsm + slot * SSTH;
        __half* Bs = As + 256 * AH;
        #pragma unroll
        for (int v = 0; v < 4; v++) {
            uint2 pk = make_uint2(pack_h2(ra[v].x, ra[v].y), pack_h2(ra[v].z, ra[v].w));
            *reinterpret_cast<uint2*>(&As[(v * 64 + srow) * AH + sc4]) = pk;
        }
        #pragma unroll
        for (int v = 0; v < NB; v++) {
            uint2 pk = make_uint2(pack_h2(rb[v].x, rb[v].y), pack_h2(rb[v].z, rb[v].w));
            *reinterpret_cast<uint2*>(&Bs[(v * 64 + srow) * AH + sc4]) = pk;
        }
    };

    float4 ra[4], rb[NB];
    // prologue: tile 0
    {
        #pragma unroll
        for (int v = 0; v < 4; v++)
            ra[v] = *reinterpret_cast<const float4*>(A + (size_t)(cRow + v * 64 + srow) * K + sc4);
        #pragma unroll
        for (int v = 0; v < NB; v++)
            rb[v] = bok[v] ? *reinterpret_cast<const float4*>(B + (size_t)(cCol + v * 64 + srow) * K + sc4)
                           : make_float4(0.f, 0.f, 0.f, 0.f);
        store_stage(0, ra, rb);
    }
    __syncthreads();

    for (int kt = 0; kt < KT; kt++) {
        const int b = kt & 1;
        const bool more = (kt + 1 < KT);
        if (more) {
            const int kb = (kt + 1) << 4;
            #pragma unroll
            for (int v = 0; v < 4; v++)
                ra[v] = *reinterpret_cast<const float4*>(A + (size_t)(cRow + v * 64 + srow) * K + kb + sc4);
            #pragma unroll
            for (int v = 0; v < NB; v++)
                rb[v] = bok[v] ? *reinterpret_cast<const float4*>(B + (size_t)(cCol + v * 64 + srow) * K + kb + sc4)
                               : make_float4(0.f, 0.f, 0.f, 0.f);
        }

        const __half* As = hsm + b * SSTH;
        const __half* Bs = As + 256 * AH;
        const int k0 = tig * 2;
        uint32_t af[4][4], bf[NFRAG][2];
        #pragma unroll
        for (int mi = 0; mi < 4; mi++) {
            const int r = wM + mi * 16 + gID;
            af[mi][0] = *reinterpret_cast<const uint32_t*>(&As[r * AH + k0]);
            af[mi][1] = *reinterpret_cast<const uint32_t*>(&As[(r + 8) * AH + k0]);
            af[mi][2] = *reinterpret_cast<const uint32_t*>(&As[r * AH + k0 + 8]);
            af[mi][3] = *reinterpret_cast<const uint32_t*>(&As[(r + 8) * AH + k0 + 8]);
        }
        #pragma unroll
        for (int ni = 0; ni < NFRAG; ni++) {
            const int r = wN + ni * 8 + gID;
            bf[ni][0] = *reinterpret_cast<const uint32_t*>(&Bs[r * AH + k0]);
            bf[ni][1] = *reinterpret_cast<const uint32_t*>(&Bs[r * AH + k0 + 8]);
        }
        #pragma unroll
        for (int mi = 0; mi < 4; mi++)
            #pragma unroll
            for (int ni = 0; ni < NFRAG; ni++)
                mma_f16(acc[mi][ni], af[mi], bf[ni]);

        if (more) store_stage(b ^ 1, ra, rb);
        __syncthreads();
    }

    // epilogue
    #pragma unroll
    for (int mi = 0; mi < 4; mi++) {
        const int r0 = cRow + wM + mi * 16 + gID;
        #pragma unroll
        for (int ni = 0; ni < NFRAG; ni++) {
            const int c = cCol + wN + ni * 8 + tig * 2;
            if (c < Nvalid) {
                *reinterpret_cast<float2*>(C + (size_t)r0 * ldC + c) =
                    make_float2(acc[mi][ni][0], acc[mi][ni][1]);
                *reinterpret_cast<float2*>(C + (size_t)(r0 + 8) * ldC + c) =
                    make_float2(acc[mi][ni][2], acc[mi][ni][3]);
            }
        }
    }
}

#define SMEM_NT128 (2 * (256 + 128) * AH * 2)   // 30720 B
#define SMEM_NT64  (2 * (256 + 64) * AH * 2)    // 25600 B

// ---------------- causal depthwise conv (K=4) + SiLU ----------------
__global__ void __launch_bounds__(256) conv_silu_kernel(const float* __restrict__ w) {
    size_t idx = (size_t)blockIdx.x * 256 + threadIdx.x;
    int c = (int)(idx % CONVD);
    int bl = (int)(idx / CONVD);
    int l = bl & (LSEQ - 1);
    float acc = 0.f;
    #pragma unroll
    for (int k = 0; k < 4; k++) {
        int lo = l - 3 + k;
        if (lo >= 0)
            acc += g_zx[(size_t)(bl - 3 + k) * DINn + HIDC + c] * w[c * 4 + k];
    }
    float s = 1.f / (1.f + expf(-acc));
    g_conv[(size_t)bl * CONVD + c] = acc * s;
}

// ---------------- dt = softplus(dt_raw + bias) ----------------
__global__ void __launch_bounds__(256) dt_kernel(const float* __restrict__ dt_bias) {
    int idx = blockIdx.x * 256 + threadIdx.x;
    int h = idx & 63;
    int bl = idx >> 6;
    float v = g_zx[(size_t)bl * DINn + (HIDC + CONVD) + h] + dt_bias[h];
    float d = (v > 20.f) ? v : log1pf(expf(v));
    g_dt[idx] = d;
}

// ---------------- per-chunk cumsum of dt*A (smem staged) ----------------
__global__ void __launch_bounds__(256) cum_kernel(const float* __restrict__ A_log) {
    __shared__ float s[QC * NHh];
    const int ch = blockIdx.x, tid = threadIdx.x;
    for (int idx = tid; idx < QC * NHh; idx += 256)
        s[idx] = g_dt[ch * QC * NHh + idx];
    __syncthreads();
    if (tid < NHh) {
        const float Ax = -expf(A_log[tid]);
        float run = 0.f;
        #pragma unroll 4
        for (int q = 0; q < QC; q++) {
            run += s[q * NHh + tid] * Ax;
            s[q * NHh + tid] = run;
        }
    }
    __syncthreads();
    for (int idx = tid; idx < QC * NHh; idx += 256)
        g_cum[ch * QC * NHh + idx] = s[idx];
}

// ---------------- per-chunk CB[i][j] = sum_n C[i,n]*B[j,n] ----------------
__global__ void __launch_bounds__(256) cb_kernel() {
    extern __shared__ float sh[];
    float* Bsh = sh;             // 128 x 129
    float* Csh = sh + 16512;     // 128 x 129
    int ch = blockIdx.x;
    int tid = threadIdx.x;
    for (int idx = tid; idx < 16384; idx += 256) {
        int i = idx >> 7, n = idx & 127;
        size_t row = (size_t)(ch * QC + i) * CONVD;
        Bsh[i * 129 + n] = g_conv[row + HIDC + n];
        Csh[i * 129 + n] = g_conv[row + HIDC + NS + n];
    }
    __syncthreads();
    int tx = tid & 15, ty = tid >> 4;
    float acc[8][8];
    #pragma unroll
    for (int i = 0; i < 8; i++)
        #pragma unroll
        for (int j = 0; j < 8; j++) acc[i][j] = 0.f;
    for (int n = 0; n < NS; n++) {
        float a[8], b[8];
        #pragma unroll
        for (int u = 0; u < 8; u++) a[u] = Csh[(ty * 8 + u) * 129 + n];
        #pragma unroll
        for (int u = 0; u < 8; u++) b[u] = Bsh[(tx * 8 + u) * 129 + n];
        #pragma unroll
        for (int i = 0; i < 8; i++)
            #pragma unroll
            for (int j = 0; j < 8; j++) acc[i][j] += a[i] * b[j];
    }
    #pragma unroll
    for (int i = 0; i < 8; i++)
        #pragma unroll
        for (int j0 = 0; j0 < 8; j0 += 4)
            *reinterpret_cast<float4*>(&g_CB[ch * 16384 + (ty * 8 + i) * 128 + tx * 8 + j0]) =
                make_float4(acc[i][j0], acc[i][j0 + 1], acc[i][j0 + 2], acc[i][j0 + 3]);
}

// ---------------- chunk states: states[h,p,n] = sum_q wdec[q]*xs[q,p]*B[q,n] ----------------
__global__ void __launch_bounds__(256) states_kernel() {
    __shared__ float Bs[32 * 128];
    __shared__ float xss[32 * 64];
    __shared__ float wdec[128];
    __shared__ float cl;
    const int h = blockIdx.x, ch = blockIdx.y;
    const int tid = threadIdx.x;
    if (tid == 0) cl = g_cum[(ch * QC + QC - 1) * NHh + h];
    __syncthreads();
    if (tid < 128) {
        int r = (ch * QC + tid) * NHh + h;
        wdec[tid] = __expf(cl - g_cum[r]) * g_dt[r];
    }
    const int p = tid >> 2, ng = tid & 3;
    uint64_t acc2[8][2];
    #pragma unroll
    for (int u = 0; u < 8; u++) { acc2[u][0] = 0ull; acc2[u][1] = 0ull; }

    for (int qt = 0; qt < 4; qt++) {
        __syncthreads();
        for (int idx = tid; idx < 4096; idx += 256) {
            int qq = idx >> 7, n = idx & 127;
            Bs[idx] = g_conv[(size_t)(ch * QC + qt * 32 + qq) * CONVD + HIDC + n];
        }
        for (int idx = tid; idx < 2048; idx += 256) {
            int qq = idx >> 6, pp = idx & 63;
            xss[idx] = g_conv[(size_t)(ch * QC + qt * 32 + qq) * CONVD + h * PD + pp];
        }
        __syncthreads();
        #pragma unroll 4
        for (int qq = 0; qq < 32; qq++) {
            const uint64_t cd = dupf(wdec[qt * 32 + qq] * xss[qq * 64 + p]);
            const float4* bp = (const float4*)&Bs[qq * 128 + ng * 32];
            #pragma unroll
            for (int u = 0; u < 8; u++) fma4p(acc2[u], cd, bp + u);
        }
    }
    size_t base = ((size_t)ch * NHh + h) * (PD * NS) + (size_t)p * NS + ng * 32;
    #pragma unroll
    for (int u = 0; u < 8; u++) {
        *reinterpret_cast<uint64_t*>(&g_states[base + u * 4])     = acc2[u][0];
        *reinterpret_cast<uint64_t*>(&g_states[base + u * 4 + 2]) = acc2[u][1];
    }
}

// ---------------- sequential inter-chunk scan (in-place: states -> Sprev) ----------------
__global__ void __launch_bounds__(256) scan_kernel() {
    const int h = blockIdx.x, b = blockIdx.y;
    const int t = threadIdx.x;
    float S[32];
    #pragma unroll
    for (int i = 0; i < 32; i++) S[i] = 0.f;
    for (int c = 0; c < 32; c++) {
        int ch = b * 32 + c;
        float dec = __expf(g_cum[(ch * QC + QC - 1) * NHh + h]);
        size_t base = ((size_t)ch * NHh + h) * (PD * NS);
        #pragma unroll
        for (int i = 0; i < 32; i++) {
            size_t id = base + (size_t)i * 256 + t;
            float st = g_states[id];
            g_states[id] = S[i];
            S[i] = S[i] * dec + st;
        }
    }
}

// ---------------- Yd + Yoff + D*xs -> y ----------------
__global__ void __launch_bounds__(256) ydyoff_kernel(const float* __restrict__ Dvec) {
    extern __shared__ float sh[];
    float* CBs   = sh;                 // 128 x 129
    float* Cs    = sh + 16512;         // 128 x 129
    float* SpT   = sh + 33024;         // [n][p] 128 x 64
    float* xss   = sh + 41216;         // [j][p] 128 x 64
    float* cum_s = sh + 49408;         // 128
    float* dt_s  = sh + 49536;         // 128
    const int h = blockIdx.x, ch = blockIdx.y, tid = threadIdx.x;

    for (int idx = tid; idx < 16384; idx += 256) {
        int i = idx >> 7, j = idx & 127;
        CBs[i * 129 + j] = g_CB[ch * 16384 + idx];
        Cs[i * 129 + j]  = g_conv[(size_t)(ch * QC + i) * CONVD + HIDC + NS + j];
    }
    for (int idx = tid; idx < 8192; idx += 256) {
        int p = idx >> 7, n = idx & 127;
        SpT[n * 64 + p] = g_states[((size_t)ch * NHh + h) * (PD * NS) + idx];
        xss[idx] = g_conv[(size_t)(ch * QC + (idx >> 6)) * CONVD + h * PD + (idx & 63)];
    }
    if (tid < 128) {
        int r = (ch * QC + tid) * NHh + h;
        cum_s[tid] = g_cum[r];
        dt_s[tid]  = g_dt[r];
    }
    __syncthreads();

    const int i = tid >> 1, ph = tid & 1;
    uint64_t aD2[8][2], aO2[8][2];
    #pragma unroll
    for (int u = 0; u < 8; u++) {
        aD2[u][0] = aD2[u][1] = 0ull;
        aO2[u][0] = aO2[u][1] = 0ull;
    }
    const float ci = cum_s[i];

    // intra-chunk (lower-triangular) attention
    for (int j = 0; j <= i; j++) {
        const uint64_t md = dupf(CBs[i * 129 + j] * __expf(ci - cum_s[j]) * dt_s[j]);
        const float4* xr = (const float4*)&xss[j * 64 + ph * 32];
        #pragma unroll
        for (int u = 0; u < 8; u++) fma4p(aD2[u], md, xr + u);
    }
    // carried-state contribution
    #pragma unroll 4
    for (int n = 0; n < NS; n++) {
        const uint64_t cd = dupf(Cs[i * 129 + n]);
        const float4* sr = (const float4*)&SpT[n * 64 + ph * 32];
        #pragma unroll
        for (int u = 0; u < 8; u++) fma4p(aO2[u], cd, sr + u);
    }
    const float ei = __expf(ci);
    const float Dh = Dvec[h];
    const float* xi = &xss[i * 64 + ph * 32];
    float* yo = &g_y[(size_t)(ch * QC + i) * HIDC + h * PD + ph * 32];
    #pragma unroll
    for (int u = 0; u < 8; u++) {
        const float* d = reinterpret_cast<const float*>(aD2[u]);
        const float* o = reinterpret_cast<const float*>(aO2[u]);
        float4 r;
        r.x = d[0] + ei * o[0] + Dh * xi[u * 4 + 0];
        r.y = d[1] + ei * o[1] + Dh * xi[u * 4 + 1];
        r.z = d[2] + ei * o[2] + Dh * xi[u * 4 + 2];
        r.w = d[3] + ei * o[3] + Dh * xi[u * 4 + 3];
        *reinterpret_cast<float4*>(&yo[u * 4]) = r;
    }
}

// ---------------- gate with silu(z) + RMSNorm (in-place on g_y) ----------------
__global__ void __launch_bounds__(256) gating_kernel(const float* __restrict__ norm_w) {
    __shared__ float red[256];
    const int bl = blockIdx.x, tid = threadIdx.x;
    float vals[16];
    float ss = 0.f;
    #pragma unroll
    for (int it = 0; it < 16; it++) {
        int idx = it * 256 + tid;
        float yv = g_y[(size_t)bl * HIDC + idx];
        float z  = g_zx[(size_t)bl * DINn + idx];
        float yz = yv * (z / (1.f + expf(-z)));
        vals[it] = yz;
        ss += yz * yz;
    }
    red[tid] = ss;
    __syncthreads();
    for (int s = 128; s > 0; s >>= 1) {
        if (tid < s) red[tid] += red[tid + s];
        __syncthreads();
    }
    float sc = rsqrtf(red[0] / (float)HIDC + 1e-5f);
    #pragma unroll
    for (int it = 0; it < 16; it++) {
        int idx = it * 256 + tid;
        g_y[(size_t)bl * HIDC + idx] = vals[it] * sc * norm_w[idx];
    }
}

// ---------------- launch ----------------
extern "C" void kernel_launch(void* const* d_in, const int* in_sizes, int n_in,
                              void* d_out, int out_size) {
    const float* x       = (const float*)d_in[0];
    const float* W_in    = (const float*)d_in[1];
    const float* conv_w  = (const float*)d_in[2];
    const float* dt_bias = (const float*)d_in[3];
    const float* A_log   = (const float*)d_in[4];
    const float* Dv      = (const float*)d_in[5];
    const float* norm_w  = (const float*)d_in[6];
    const float* W_out   = (const float*)d_in[7];
    float* out = (float*)d_out;

    float *zx_p, *y_p;
    cudaGetSymbolAddress((void**)&zx_p, g_zx);
    cudaGetSymbolAddress((void**)&y_p, g_y);

    static cudaStream_t s2 = nullptr;
    static cudaEvent_t evA = nullptr, evB = nullptr;
    if (s2 == nullptr) {
        cudaStreamCreateWithFlags(&s2, cudaStreamNonBlocking);
        cudaEventCreateWithFlags(&evA, cudaEventDisableTiming);
        cudaEventCreateWithFlags(&evB, cudaEventDisableTiming);
        cudaFuncSetAttribute(gemm_tc<128>, cudaFuncAttributeMaxDynamicSharedMemorySize, SMEM_NT128);
        cudaFuncSetAttribute(gemm_tc<64>,  cudaFuncAttributeMaxDynamicSharedMemorySize, SMEM_NT64);
        cudaFuncSetAttribute(cb_kernel, cudaFuncAttributeMaxDynamicSharedMemorySize, 132096);
        cudaFuncSetAttribute(ydyoff_kernel, cudaFuncAttributeMaxDynamicSharedMemorySize, 198656);
    }

    // 1a) in-proj GEMM, xBC+dt columns [4096, 8512)
    gemm_tc<128><<<dim3(35, 32), 256, SMEM_NT128>>>(
        x, W_in + (size_t)HIDC * DIMI, zx_p + HIDC, DINn - HIDC, DIMI, DINn);
    cudaEventRecord(evA, 0);

    // 1b) in-proj GEMM, z columns [0, 4096) — side stream, overlapped with mid-chain
    cudaStreamWaitEvent(s2, evA, 0);
    gemm_tc<128><<<dim3(32, 32), 256, SMEM_NT128, s2>>>(
        x, W_in, zx_p, HIDC, DIMI, DINn);
    cudaEventRecord(evB, s2);

    // mid-chain on default stream (concurrent with 1b)
    conv_silu_kernel<<<(BLn * CONVD) / 256, 256>>>(conv_w);
    dt_kernel<<<(BLn * NHh) / 256, 256>>>(dt_bias);
    cum_kernel<<<NCT, 256>>>(A_log);
    cb_kernel<<<NCT, 256, 132096>>>();
    states_kernel<<<dim3(NHh, NCT), 256>>>();
    scan_kernel<<<dim3(NHh, 2), 256>>>();
    ydyoff_kernel<<<dim3(NHh, NCT), 256, 198656>>>(Dv);

    // join: gating needs z columns from 1b
    cudaStreamWaitEvent(0, evB, 0);
    gating_kernel<<<BLn, 256>>>(norm_w);

    // 2) out-proj GEMM: (8192 x 4096) * (2048 x 4096)^T — NT=64 for wave balance
    gemm_tc<64><<<dim3(32, 32), 256, SMEM_NT64>>>(y_p, W_out, out, DIMI, HIDC, DIMI);
}